// round 13
// baseline (speedup 1.0000x reference)
#include <cuda_runtime.h>
#include <cuda_fp16.h>
#include <cstdint>

#define BATCH 8192
#define NREF  2048
#define KDIM  256
#define MT    128             // M rows per mtile
#define NM    64              // mtiles
#define TCOLS 640             // packed cols (tensor refs 0..1279, 2 per col)
#define TCHUNKS 20            // 32-col chunks per mtile slice
#define NT    32
#define PREFS 768             // popc refs 1280..2047
#define PBLK  6               // popc ref blocks of 128
#define GRID  296
#define ROWB  512
#define LDB   528

__device__ __half    g_Bp[TCOLS * KDIM];     // radix-1024 packed, k-permuted
__device__ float     g_cntR[2 * TCOLS];      // cntR for tensor refs (1280)
__device__ uint32_t  g_Sbits[BATCH * 8];     // S rows as 256-bit
__device__ uint32_t  g_Rbits[PREFS * 8];     // popc R rows as 256-bit

struct SmemT { char B[3][NT * LDB]; float cntR[2 * TCOLS]; };  // 50688+5120
struct SmemP { uint32_t Rb[128 * 8]; };                        // 4096
union  Smem  { SmemT t; SmemP p; };
#define SMEM_SZ (int)sizeof(Smem)

// ---------------------------------------------------------------------------
__device__ __forceinline__ uint32_t s2u(const void* p) {
    uint32_t a;
    asm("{ .reg .u64 t; cvta.to.shared.u64 t, %1; cvt.u32.u64 %0, t; }" : "=r"(a) : "l"(p));
    return a;
}
__device__ __forceinline__ void cpa16(uint32_t dst, const void* src) {
    asm volatile("cp.async.cg.shared.global [%0], [%1], 16;" :: "r"(dst), "l"(src));
}
template <int N>
__device__ __forceinline__ void cpwait() {
    asm volatile("cp.async.wait_group %0;" :: "n"(N) : "memory");
}
__device__ __forceinline__ void mma_f16f32(float* c, const uint32_t* a,
                                           uint32_t b0, uint32_t b1) {
    asm volatile(
        "mma.sync.aligned.m16n8k16.row.col.f32.f16.f16.f32 "
        "{%0,%1,%2,%3},{%4,%5,%6,%7},{%8,%9},{%0,%1,%2,%3};"
        : "+f"(c[0]), "+f"(c[1]), "+f"(c[2]), "+f"(c[3])
        : "r"(a[0]), "r"(a[1]), "r"(a[2]), "r"(a[3]), "r"(b0), "r"(b1));
}
__device__ __forceinline__ uint32_t packh2(float x, float y) {
    __half2 h = __floats2half2_rn(x, y);
    return *reinterpret_cast<uint32_t*>(&h);
}
__device__ __forceinline__ void decode_min(float acc, float2 cr, float& rmin) {
    float d1 = rintf(acc * (1.0f / 1024.0f));   // |d0|/1024 <= 0.25 -> no ties
    float d0 = fmaf(d1, -1024.0f, acc);         // exact
    rmin = fminf(rmin, fminf(d0 + cr.x, d1 + cr.y));
}

// ---------------------------------------------------------------------------
// Prep: out init; pack tensor refs (radix-1024, k-permuted); cntR; bit-pack
// S rows and popc R rows (thread-per-word, no ballots). All exact.
// segments: [0,40960) pack | [40960,81920) cntR | [81920,147456) Sbits |
//           [147456,153600) Rbits ; out-init rides on i<8192.
// ---------------------------------------------------------------------------
#define PREP_T 153600

__global__ void prep_kernel(const float* __restrict__ S, const float* __restrict__ R,
                            int* __restrict__ outi) {
    int i = blockIdx.x * 256 + threadIdx.x;

    if (i < BATCH) outi[i] = 0x7f800000;        // +inf bits

    if (i < 40960) {                            // pack: col j = i>>6 < 640
        int j = i >> 6, c = i & 63;
        int g16 = c >> 2, q = c & 3;
        float4 r0 = *reinterpret_cast<const float4*>(R + (size_t)(2 * j) * KDIM + c * 4);
        float4 r1 = *reinterpret_cast<const float4*>(R + (size_t)(2 * j + 1) * KDIM + c * 4);
        uint32_t lo = packh2(1025.f - 2.f * r0.x - 2048.f * r1.x,
                             1025.f - 2.f * r0.y - 2048.f * r1.y);
        uint32_t hi = packh2(1025.f - 2.f * r0.z - 2048.f * r1.z,
                             1025.f - 2.f * r0.w - 2048.f * r1.w);
        uint32_t* bp = reinterpret_cast<uint32_t*>(g_Bp);
        bp[j * 128 + g16 * 8 + q]     = lo;
        bp[j * 128 + g16 * 8 + 4 + q] = hi;
    } else if (i < 81920) {                     // cntR for refs 0..1279
        int t = i - 40960;
        int w = t >> 5, lane = t & 31;
        float s = 0.f;
        #pragma unroll
        for (int k = lane; k < KDIM; k += 32) s += R[(size_t)w * KDIM + k];
        #pragma unroll
        for (int o = 16; o; o >>= 1) s += __shfl_xor_sync(0xffffffffu, s, o);
        if (lane == 0) g_cntR[w] = s;
    } else if (i < 147456) {                    // S bits: thread per 32-bit word
        int t = i - 81920;                      // < 65536
        int row = t >> 3, w = t & 7;
        const float4* src = reinterpret_cast<const float4*>(S + (size_t)row * KDIM + w * 32);
        uint32_t bword = 0;
        #pragma unroll
        for (int k2 = 0; k2 < 8; k2++) {
            float4 v = src[k2];
            bword |= ((uint32_t)v.x) << (k2 * 4 + 0);
            bword |= ((uint32_t)v.y) << (k2 * 4 + 1);
            bword |= ((uint32_t)v.z) << (k2 * 4 + 2);
            bword |= ((uint32_t)v.w) << (k2 * 4 + 3);
        }
        g_Sbits[row * 8 + w] = bword;
    } else if (i < PREP_T) {                    // R bits for refs 1280..2047
        int t = i - 147456;                     // < 6144
        int pr = t >> 3, w = t & 7;
        const float4* src = reinterpret_cast<const float4*>(
            R + (size_t)(2 * TCOLS + pr) * KDIM + w * 32);
        uint32_t bword = 0;
        #pragma unroll
        for (int k2 = 0; k2 < 8; k2++) {
            float4 v = src[k2];
            bword |= ((uint32_t)v.x) << (k2 * 4 + 0);
            bword |= ((uint32_t)v.y) << (k2 * 4 + 1);
            bword |= ((uint32_t)v.z) << (k2 * 4 + 2);
            bword |= ((uint32_t)v.w) << (k2 * 4 + 3);
        }
        g_Rbits[pr * 8 + w] = bword;
    }
}

// ---------------------------------------------------------------------------
// Main: per-CTA two phases (tensor HMMA on 1280 refs; popc on 768 refs),
// wave-staggered so the SM's two CTAs occupy opposite pipes.
// ---------------------------------------------------------------------------
__device__ __forceinline__ void load_B(Smem& sm, int item, int buf, int tid) {
    int chunk = item % TCHUNKS;
    const char* src = (const char*)g_Bp + (size_t)chunk * NT * ROWB;
    #pragma unroll
    for (int j = 0; j < 8; j++) {
        int i = tid + j * 128;
        int r = i >> 5, c = i & 31;
        cpa16(s2u(&sm.t.B[buf][r * LDB + c * 16]), src + (size_t)r * ROWB + c * 16);
    }
    asm volatile("cp.async.commit_group;" ::: "memory");
}

__global__ void __launch_bounds__(128, 2) hamming_hb(const float* __restrict__ S,
                                                     int* __restrict__ outi) {
    extern __shared__ __align__(16) char smraw[];
    Smem& sm = *reinterpret_cast<Smem*>(smraw);

    const int tid  = threadIdx.x;
    const int wid  = tid >> 5;
    const int lane = tid & 31;
    const int g    = lane >> 2;
    const int q    = lane & 3;
    const int b    = blockIdx.x;

    // =================== popc phase ===================
    auto popc_phase = [&]() {
        const int ps = (b * 48) / 37, pe = ((b + 1) * 48) / 37;   // over 384 items
        for (int pit = ps; pit < pe; pit++) {
            int m = pit / PBLK, rb = pit % PBLK;
            __syncthreads();                    // smem reuse guard
            {
                const uint4* gsrc = reinterpret_cast<const uint4*>(
                    g_Rbits + (size_t)rb * 128 * 8);
                uint4* Rb4 = reinterpret_cast<uint4*>(sm.p.Rb);
                for (int i = tid; i < 256; i += 128) Rb4[i] = gsrc[i];
            }
            __syncthreads();
            const uint4* Rb4 = reinterpret_cast<const uint4*>(sm.p.Rb);
            int grow = m * MT + wid * 32 + lane;
            const uint4* sp = reinterpret_cast<const uint4*>(g_Sbits + (size_t)grow * 8);
            uint4 s0 = sp[0], s1 = sp[1];
            int vmin = 0x7fffffff;
            #pragma unroll 4
            for (int j = 0; j < 128; j++) {
                uint4 r0 = Rb4[j * 2], r1 = Rb4[j * 2 + 1];
                int d = __popc(s0.x ^ r0.x) + __popc(s0.y ^ r0.y)
                      + __popc(s0.z ^ r0.z) + __popc(s0.w ^ r0.w)
                      + __popc(s1.x ^ r1.x) + __popc(s1.y ^ r1.y)
                      + __popc(s1.z ^ r1.z) + __popc(s1.w ^ r1.w);
                vmin = min(vmin, d);
            }
            atomicMin(&outi[grow], __float_as_int((float)vmin));
        }
    };

    // =================== tensor phase ===================
    auto tensor_phase = [&]() {
        const int start = (b * 160) / 37, end = ((b + 1) * 160) / 37;  // over 1280
        int cur_m = start / TCHUNKS;

        load_B(sm, start, 0, tid);
        if (start + 1 < end) load_B(sm, start + 1, 1, tid);

        uint32_t a[2][16][4];
        auto loadA = [&](int m) {
            #pragma unroll
            for (int mt = 0; mt < 2; mt++) {
                const float* rowLo = S + ((size_t)(m * MT + wid * 32 + mt * 16 + g)) * KDIM;
                const float* rowHi = rowLo + 8 * KDIM;
                #pragma unroll
                for (int ks = 0; ks < 16; ks++) {
                    float4 v0 = *reinterpret_cast<const float4*>(rowLo + ks * 16 + q * 4);
                    float4 v1 = *reinterpret_cast<const float4*>(rowHi + ks * 16 + q * 4);
                    a[mt][ks][0] = packh2(v0.x, v0.y);
                    a[mt][ks][2] = packh2(v0.z, v0.w);
                    a[mt][ks][1] = packh2(v1.x, v1.y);
                    a[mt][ks][3] = packh2(v1.z, v1.w);
                }
            }
        };
        loadA(cur_m);

        for (int i = tid; i < (2 * TCOLS) / 4; i += 128)
            *reinterpret_cast<float4*>(&sm.t.cntR[i * 4]) =
                *reinterpret_cast<const float4*>(&g_cntR[i * 4]);

        const float2* cr2 = reinterpret_cast<const float2*>(sm.t.cntR);
        float rmin[2][2] = {{__int_as_float(0x7f800000), __int_as_float(0x7f800000)},
                            {__int_as_float(0x7f800000), __int_as_float(0x7f800000)}};

        auto flush = [&](int m) {
            #pragma unroll
            for (int mt = 0; mt < 2; mt++)
                #pragma unroll
                for (int h = 0; h < 2; h++) {
                    float v = rmin[mt][h];
                    v = fminf(v, __shfl_xor_sync(0xffffffffu, v, 1));
                    v = fminf(v, __shfl_xor_sync(0xffffffffu, v, 2));
                    if (q == 0)
                        atomicMin(&outi[m * MT + wid * 32 + mt * 16 + h * 8 + g],
                                  __float_as_int(v));
                    rmin[mt][h] = __int_as_float(0x7f800000);
                }
        };

        for (int it = start; it < end; it++) {
            if (it + 1 < end) cpwait<1>(); else cpwait<0>();
            __syncthreads();
            if (it + 2 < end) load_B(sm, it + 2, (it + 2 - start) % 3, tid);

            const char* Bb = sm.t.B[(it - start) % 3];
            float c[2][4][4];
            #pragma unroll
            for (int mt = 0; mt < 2; mt++)
                #pragma unroll
                for (int u = 0; u < 4; u++)
                    c[mt][u][0] = c[mt][u][1] = c[mt][u][2] = c[mt][u][3] = 0.f;

            #pragma unroll
            for (int ks = 0; ks < 16; ks++) {
                int kb = ks * 32 + q * 4;
                uint32_t b0[4], b1[4];
                #pragma unroll
                for (int u = 0; u < 4; u++) {
                    const char* bp = &Bb[(u * 8 + g) * LDB + kb];
                    b0[u] = *reinterpret_cast<const uint32_t*>(bp);
                    b1[u] = *reinterpret_cast<const uint32_t*>(bp + 16);
                }
                #pragma unroll
                for (int u = 0; u < 4; u++) {
                    mma_f16f32(c[0][u], a[0][ks], b0[u], b1[u]);
                    mma_f16f32(c[1][u], a[1][ks], b0[u], b1[u]);
                }
            }

            int cc = it % TCHUNKS;
            #pragma unroll
            for (int u = 0; u < 4; u++) {
                int gcol = cc * NT + u * 8 + q * 2;
                float2 cra = cr2[gcol];
                float2 crb = cr2[gcol + 1];
                #pragma unroll
                for (int mt = 0; mt < 2; mt++) {
                    decode_min(c[mt][u][0], cra, rmin[mt][0]);
                    decode_min(c[mt][u][1], crb, rmin[mt][0]);
                    decode_min(c[mt][u][2], cra, rmin[mt][1]);
                    decode_min(c[mt][u][3], crb, rmin[mt][1]);
                }
            }

            if (it + 1 < end) {
                int nm = (it + 1) / TCHUNKS;
                if (nm != cur_m) { flush(cur_m); loadA(nm); cur_m = nm; }
            }
        }
        flush(cur_m);
    };

    // wave-staggered phase order: the SM's two co-resident CTAs (b, b+148)
    // run opposite phases, keeping tensor and alu pipes simultaneously fed.
    if (b < 148) {
        tensor_phase();
        popc_phase();
    } else {
        popc_phase();
        __syncthreads();
        tensor_phase();
    }
}

// ---------------------------------------------------------------------------
extern "C" void kernel_launch(void* const* d_in, const int* in_sizes, int n_in,
                              void* d_out, int out_size) {
    const float* states = (const float*)d_in[0];
    const float* R      = (const float*)d_in[1];
    int* outi           = (int*)d_out;

    prep_kernel<<<PREP_T / 256, 256>>>(states, R, outi);

    cudaFuncSetAttribute(hamming_hb, cudaFuncAttributeMaxDynamicSharedMemorySize, SMEM_SZ);
    hamming_hb<<<GRID, 128, SMEM_SZ>>>(states, outi);
}

// round 14
// speedup vs baseline: 1.4804x; 1.4804x over previous
#include <cuda_runtime.h>
#include <cuda_fp16.h>
#include <cstdint>

#define BATCH 8192
#define NREF  2048
#define KDIM  256
#define MT    128             // M rows per CTA (4 warps x 32 rows)
#define NPACK 1024            // packed columns total (2 refs each)
#define NQ    256             // packed cols per CTA quarter
#define NT    64              // packed cols per tile
#define NTILES (NQ / NT)      // 4
#define GRID  256             // 64 mtiles x 4 quarters; single resident wave
#define ROWB  512             // bytes per packed-col row (256 halves)
#define LDB   528             // padded smem row stride (bytes)

// g_Bp[j][k']: k-permuted f16 (1-2R[2j,k]) + 1024*(1-2R[2j+1,k])
__device__ __half g_Bp[NPACK * KDIM];
__device__ float  g_cntR[NREF];
__device__ unsigned int g_bar;          // monotonic global-barrier counter

struct Smem {
    char  B[2][NT * LDB];     // 2 x 33792 B
    float cntR[2 * NQ];       // this quarter's 512 cntR
};
#define SMEM_SZ (int)sizeof(Smem)

// ---------------------------------------------------------------------------
__device__ __forceinline__ uint32_t s2u(const void* p) {
    uint32_t a;
    asm("{ .reg .u64 t; cvta.to.shared.u64 t, %1; cvt.u32.u64 %0, t; }" : "=r"(a) : "l"(p));
    return a;
}
__device__ __forceinline__ void cpa16(uint32_t dst, const void* src) {
    asm volatile("cp.async.cg.shared.global [%0], [%1], 16;" :: "r"(dst), "l"(src));
}
template <int N>
__device__ __forceinline__ void cpwait() {
    asm volatile("cp.async.wait_group %0;" :: "n"(N) : "memory");
}
__device__ __forceinline__ void mma_f16f32(float* c, const uint32_t* a,
                                           uint32_t b0, uint32_t b1) {
    asm volatile(
        "mma.sync.aligned.m16n8k16.row.col.f32.f16.f16.f32 "
        "{%0,%1,%2,%3},{%4,%5,%6,%7},{%8,%9},{%0,%1,%2,%3};"
        : "+f"(c[0]), "+f"(c[1]), "+f"(c[2]), "+f"(c[3])
        : "r"(a[0]), "r"(a[1]), "r"(a[2]), "r"(a[3]), "r"(b0), "r"(b1));
}
__device__ __forceinline__ uint32_t packh2(float x, float y) {
    __half2 h = __floats2half2_rn(x, y);
    return *reinterpret_cast<uint32_t*>(&h);
}
__device__ __forceinline__ void decode_min(float acc, float2 cr, float& rmin) {
    float d1 = rintf(acc * (1.0f / 1024.0f));      // |d0|/1024 <= 0.25 -> no ties
    float d0 = fmaf(d1, -1024.0f, acc);            // exact
    rmin = fminf(rmin, fminf(d0 + cr.x, d1 + cr.y));
}

// ---------------------------------------------------------------------------
// Fused kernel: [phase 0] distributed prep (out init, radix-1024 k-permuted
// B pack, cntR) -> resident-wave global barrier -> [phase 1] R9 HMMA GEMM.
// ---------------------------------------------------------------------------
__device__ __forceinline__ void load_B(Smem& sm, int t, int buf, int quarter, int tid) {
    const char* src = (const char*)g_Bp + ((size_t)(quarter * NQ + t * NT)) * ROWB;
    #pragma unroll
    for (int j = 0; j < 16; j++) {           // 2048 x 16B chunks / 128 threads
        int i = tid + j * 128;
        int r = i >> 5, c = i & 31;          // 32 chunks per 512B row
        cpa16(s2u(&sm.B[buf][r * LDB + c * 16]), src + (size_t)r * ROWB + c * 16);
    }
    asm volatile("cp.async.commit_group;" ::: "memory");
}

__global__ void __launch_bounds__(128, 2) hamming_fused(const float* __restrict__ S,
                                                        const float* __restrict__ R,
                                                        int* __restrict__ outi) {
    extern __shared__ __align__(16) char smraw[];
    Smem& sm = *reinterpret_cast<Smem*>(smraw);

    const int tid  = threadIdx.x;
    const int wid  = tid >> 5;
    const int lane = tid & 31;
    const int g    = lane >> 2;
    const int q    = lane & 3;
    const int mtile   = blockIdx.x >> 2;
    const int quarter = blockIdx.x & 3;

    // ================= phase 0: distributed prep =================
    {
        const int gtid = blockIdx.x * 128 + tid;     // 0..32767
        const int nthr = GRID * 128;

        // out init (+inf bits)
        for (int i = gtid; i < BATCH; i += nthr) outi[i] = 0x7f800000;

        // pack ref pairs: radix-1024, k-permuted (one k-quad per item)
        for (int i = gtid; i < NPACK * 64; i += nthr) {
            int j = i >> 6, c = i & 63;
            int g16 = c >> 2, qq = c & 3;
            float4 r0 = *reinterpret_cast<const float4*>(R + (size_t)(2 * j) * KDIM + c * 4);
            float4 r1 = *reinterpret_cast<const float4*>(R + (size_t)(2 * j + 1) * KDIM + c * 4);
            uint32_t lo = packh2(1025.f - 2.f * r0.x - 2048.f * r1.x,
                                 1025.f - 2.f * r0.y - 2048.f * r1.y);
            uint32_t hi = packh2(1025.f - 2.f * r0.z - 2048.f * r1.z,
                                 1025.f - 2.f * r0.w - 2048.f * r1.w);
            uint32_t* bp = reinterpret_cast<uint32_t*>(g_Bp);
            bp[j * 128 + g16 * 8 + qq]     = lo;
            bp[j * 128 + g16 * 8 + 4 + qq] = hi;
        }

        // cntR: one warp per row, 1024 warps cover 2048 rows in 2 passes
        const int gw = gtid >> 5;                    // 0..1023
        for (int w = gw; w < NREF; w += nthr / 32) {
            float s = 0.f;
            #pragma unroll
            for (int k = lane; k < KDIM; k += 32) s += R[(size_t)w * KDIM + k];
            #pragma unroll
            for (int o = 16; o; o >>= 1) s += __shfl_xor_sync(0xffffffffu, s, o);
            if (lane == 0) g_cntR[w] = s;
        }
    }

    // ================= resident-wave global barrier =================
    // grid 256 @ occupancy 2 => single wave, all CTAs co-resident: spin is safe.
    // Ticket math keeps the monotonic counter correct across graph replays.
    __syncthreads();
    __threadfence();
    if (tid == 0) {
        unsigned int ticket = atomicAdd(&g_bar, 1u);
        unsigned int target = (ticket / GRID + 1u) * GRID;
        while (*reinterpret_cast<volatile unsigned int*>(&g_bar) < target)
            __nanosleep(64);
    }
    __syncthreads();
    __threadfence();

    // ================= phase 1: HMMA GEMM (R9 structure) =================
    load_B(sm, 0, 0, quarter, tid);                  // tile 0 in flight

    // A fragments from float S: 2 m16-tiles x 16 ks x 4 regs, contiguous
    // float4 loads thanks to the k-permutation applied to B.
    uint32_t a[2][16][4];
    #pragma unroll
    for (int mt = 0; mt < 2; mt++) {
        const float* rowLo = S + ((size_t)(mtile * MT + wid * 32 + mt * 16 + g)) * KDIM;
        const float* rowHi = rowLo + 8 * KDIM;
        #pragma unroll
        for (int ks = 0; ks < 16; ks++) {
            float4 v0 = *reinterpret_cast<const float4*>(rowLo + ks * 16 + q * 4);
            float4 v1 = *reinterpret_cast<const float4*>(rowHi + ks * 16 + q * 4);
            a[mt][ks][0] = packh2(v0.x, v0.y);
            a[mt][ks][2] = packh2(v0.z, v0.w);
            a[mt][ks][1] = packh2(v1.x, v1.y);
            a[mt][ks][3] = packh2(v1.z, v1.w);
        }
    }
    // this quarter's 512 cntR values
    for (int i = tid; i < 2 * NQ; i += 128) sm.cntR[i] = g_cntR[quarter * 2 * NQ + i];

    float rmin[2][2] = {{__int_as_float(0x7f800000), __int_as_float(0x7f800000)},
                        {__int_as_float(0x7f800000), __int_as_float(0x7f800000)}};

    for (int t = 0; t < NTILES; t++) {
        if (t + 1 < NTILES) {
            load_B(sm, t + 1, (t + 1) & 1, quarter, tid);
            cpwait<1>();
        } else {
            cpwait<0>();
        }
        __syncthreads();

        const char* Bb = sm.B[t & 1];
        const float2* cr2 = reinterpret_cast<const float2*>(sm.cntR);

        #pragma unroll
        for (int grp = 0; grp < 2; grp++) {          // 2 groups of 4 n-blocks
            float c[2][4][4];
            #pragma unroll
            for (int mt = 0; mt < 2; mt++)
                #pragma unroll
                for (int u = 0; u < 4; u++)
                    c[mt][u][0] = c[mt][u][1] = c[mt][u][2] = c[mt][u][3] = 0.f;

            #pragma unroll
            for (int ks = 0; ks < 16; ks++) {
                int kb = ks * 32 + q * 4;
                uint32_t b0[4], b1[4];
                #pragma unroll
                for (int u = 0; u < 4; u++) {
                    const char* bp = &Bb[((grp * 4 + u) * 8 + g) * LDB + kb];
                    b0[u] = *reinterpret_cast<const uint32_t*>(bp);
                    b1[u] = *reinterpret_cast<const uint32_t*>(bp + 16);
                }
                #pragma unroll
                for (int u = 0; u < 4; u++) {
                    mma_f16f32(c[0][u], a[0][ks], b0[u], b1[u]);
                    mma_f16f32(c[1][u], a[1][ks], b0[u], b1[u]);
                }
            }

            // decode epilogue: each acc column carries 2 refs
            #pragma unroll
            for (int u = 0; u < 4; u++) {
                int colbase = t * NT + (grp * 4 + u) * 8 + q * 2;
                float2 cra = cr2[colbase];
                float2 crb = cr2[colbase + 1];
                #pragma unroll
                for (int mt = 0; mt < 2; mt++) {
                    decode_min(c[mt][u][0], cra, rmin[mt][0]);
                    decode_min(c[mt][u][1], crb, rmin[mt][0]);
                    decode_min(c[mt][u][2], cra, rmin[mt][1]);
                    decode_min(c[mt][u][3], crb, rmin[mt][1]);
                }
            }
        }
        __syncthreads();
    }

    // combine quads; quarters via int atomicMin on float bits (all >= 0)
    #pragma unroll
    for (int mt = 0; mt < 2; mt++) {
        #pragma unroll
        for (int h = 0; h < 2; h++) {
            float v = rmin[mt][h];
            v = fminf(v, __shfl_xor_sync(0xffffffffu, v, 1));
            v = fminf(v, __shfl_xor_sync(0xffffffffu, v, 2));
            if (q == 0)
                atomicMin(&outi[mtile * MT + wid * 32 + mt * 16 + h * 8 + g],
                          __float_as_int(v));
        }
    }
}

// ---------------------------------------------------------------------------
extern "C" void kernel_launch(void* const* d_in, const int* in_sizes, int n_in,
                              void* d_out, int out_size) {
    const float* states = (const float*)d_in[0];
    const float* R      = (const float*)d_in[1];
    int* outi           = (int*)d_out;

    cudaFuncSetAttribute(hamming_fused, cudaFuncAttributeMaxDynamicSharedMemorySize,
                         SMEM_SZ);
    hamming_fused<<<GRID, 128, SMEM_SZ>>>(states, R, outi);
}

// round 15
// speedup vs baseline: 1.7662x; 1.1931x over previous
#include <cuda_runtime.h>
#include <cuda_fp16.h>
#include <cstdint>

#define BATCH 8192
#define NREF  2048
#define KDIM  256
#define MT    128             // M rows per CTA (4 warps x 32 rows)
#define NPACK 1024            // packed columns total (2 refs each)
#define NQ    256             // packed cols per CTA quarter
#define NT    64              // packed cols per tile
#define NTILES (NQ / NT)      // 4
#define GRID  256             // 64 mtiles x 4 quarters
#define TILE_B 32768          // bytes per B tile (64 cols x 512 B)

// g_B: fragment-order layout. Per tile T (0..15):
//   [grp(2)][ksp(8)][u(4)][lane(32)] -> uint4 {b0,b1 @ks=2ksp, b0,b1 @ks=2ksp+1}
__device__ uint4 g_B[NPACK * KDIM / 8];    // 1 MB
__device__ float g_cc[NPACK];              // cntR[2n] + 1024*cntR[2n+1]

struct Smem {
    uint4 B[2][TILE_B / 16];  // 2 x 32768 B
    float cc[NQ];             // this quarter's 256 cc values
};
#define SMEM_SZ (int)sizeof(Smem)

// ---------------------------------------------------------------------------
__device__ __forceinline__ uint32_t s2u(const void* p) {
    uint32_t a;
    asm("{ .reg .u64 t; cvta.to.shared.u64 t, %1; cvt.u32.u64 %0, t; }" : "=r"(a) : "l"(p));
    return a;
}
__device__ __forceinline__ void cpa16(uint32_t dst, const void* src) {
    asm volatile("cp.async.cg.shared.global [%0], [%1], 16;" :: "r"(dst), "l"(src));
}
template <int N>
__device__ __forceinline__ void cpwait() {
    asm volatile("cp.async.wait_group %0;" :: "n"(N) : "memory");
}
__device__ __forceinline__ void mma_f16f32(float* c, const uint32_t* a,
                                           uint32_t b0, uint32_t b1) {
    asm volatile(
        "mma.sync.aligned.m16n8k16.row.col.f32.f16.f16.f32 "
        "{%0,%1,%2,%3},{%4,%5,%6,%7},{%8,%9},{%0,%1,%2,%3};"
        : "+f"(c[0]), "+f"(c[1]), "+f"(c[2]), "+f"(c[3])
        : "r"(a[0]), "r"(a[1]), "r"(a[2]), "r"(a[3]), "r"(b0), "r"(b1));
}
__device__ __forceinline__ uint32_t packh2(float x, float y) {
    __half2 h = __floats2half2_rn(x, y);
    return *reinterpret_cast<uint32_t*>(&h);
}
// decode packed distance: comb = d0 + 1024*d1, d0,d1 in [0,256] (exact)
__device__ __forceinline__ void decode_min(float acc, float ccv, float& rmin) {
    float comb = acc + ccv;
    float d1 = rintf(comb * (1.0f / 1024.0f));     // d0/1024 <= 0.25 -> no ties
    float d0 = fmaf(d1, -1024.0f, comb);           // exact
    rmin = fminf(rmin, fminf(d0, d1));
}

// ---------------------------------------------------------------------------
// Kernel 1 (prep): out init; fragment-order radix-1024 B pack; cc.
//   val(n,k) = 1025 - 2*R[2n][k] - 2048*R[2n+1][k]  in {+-1023, +-1025} (f16-exact)
// ---------------------------------------------------------------------------
__global__ void prep_kernel(const float* __restrict__ R, int* __restrict__ outi) {
    int i = blockIdx.x * 256 + threadIdx.x;      // 65536 threads

    if (i < BATCH) outi[i] = 0x7f800000;         // +inf bits

    if (i < 32768) {
        // one uint4 of fragment-order B per thread
        int T    = i >> 11;
        int r    = i & 2047;
        int grp  = r >> 10;
        int ksp  = (r >> 7) & 7;
        int u    = (r >> 5) & 3;
        int lane = r & 31;
        int g    = lane >> 2, q = lane & 3;
        int n    = T * 64 + (grp * 4 + u) * 8 + g;   // packed col
        int kk0  = ksp * 32 + q * 4;

        const float* r0 = R + (size_t)(2 * n) * KDIM;
        const float* r1 = r0 + KDIM;
        float4 a0 = *reinterpret_cast<const float4*>(r0 + kk0);
        float4 a1 = *reinterpret_cast<const float4*>(r0 + kk0 + 16);
        float4 b0 = *reinterpret_cast<const float4*>(r1 + kk0);
        float4 b1 = *reinterpret_cast<const float4*>(r1 + kk0 + 16);

        uint4 o;
        o.x = packh2(1025.f - 2.f * a0.x - 2048.f * b0.x,
                     1025.f - 2.f * a0.y - 2048.f * b0.y);
        o.y = packh2(1025.f - 2.f * a0.z - 2048.f * b0.z,
                     1025.f - 2.f * a0.w - 2048.f * b0.w);
        o.z = packh2(1025.f - 2.f * a1.x - 2048.f * b1.x,
                     1025.f - 2.f * a1.y - 2048.f * b1.y);
        o.w = packh2(1025.f - 2.f * a1.z - 2048.f * b1.z,
                     1025.f - 2.f * a1.w - 2048.f * b1.w);
        g_B[i] = o;
    } else {
        // cc: one warp per packed col (1024 warps)
        int t = i - 32768;
        int n = t >> 5, lane = t & 31;
        const float* r0 = R + (size_t)(2 * n) * KDIM;
        float s0 = 0.f, s1 = 0.f;
        #pragma unroll
        for (int k = lane; k < KDIM; k += 32) {
            s0 += r0[k];
            s1 += r0[KDIM + k];
        }
        float s = s0 + 1024.f * s1;
        #pragma unroll
        for (int o = 16; o; o >>= 1) s += __shfl_xor_sync(0xffffffffu, s, o);
        if (lane == 0) g_cc[n] = s;
    }
}

// ---------------------------------------------------------------------------
// Kernel 2 (main): HMMA on fragment-order B -> 64 LDS.128 per tile
// (was 256 LDS.32). A fragments in registers; 2-buffer cp.async; decode min.
// ---------------------------------------------------------------------------
__device__ __forceinline__ void load_B(Smem& sm, int T, int buf, int tid) {
    const char* src = (const char*)g_B + (size_t)T * TILE_B;
    uint32_t dst = s2u(&sm.B[buf][0]);
    #pragma unroll
    for (int j = 0; j < 16; j++) {           // 2048 x 16B / 128 threads
        int i = tid + j * 128;
        cpa16(dst + i * 16, src + (size_t)i * 16);
    }
    asm volatile("cp.async.commit_group;" ::: "memory");
}

__global__ void __launch_bounds__(128, 2) hamming_fr(const float* __restrict__ S,
                                                     int* __restrict__ outi) {
    extern __shared__ __align__(16) char smraw[];
    Smem& sm = *reinterpret_cast<Smem*>(smraw);

    const int tid  = threadIdx.x;
    const int wid  = tid >> 5;
    const int lane = tid & 31;
    const int g    = lane >> 2;
    const int q    = lane & 3;
    const int mtile   = blockIdx.x >> 2;
    const int quarter = blockIdx.x & 3;

    load_B(sm, quarter * NTILES, 0, tid);        // tile 0 in flight

    // A fragments: 2 m16-tiles x 16 ks x 4 regs, contiguous float4 loads
    // (k-permutation is baked into B's fragment layout)
    uint32_t a[2][16][4];
    #pragma unroll
    for (int mt = 0; mt < 2; mt++) {
        const float* rowLo = S + ((size_t)(mtile * MT + wid * 32 + mt * 16 + g)) * KDIM;
        const float* rowHi = rowLo + 8 * KDIM;
        #pragma unroll
        for (int ks = 0; ks < 16; ks++) {
            float4 v0 = *reinterpret_cast<const float4*>(rowLo + ks * 16 + q * 4);
            float4 v1 = *reinterpret_cast<const float4*>(rowHi + ks * 16 + q * 4);
            a[mt][ks][0] = packh2(v0.x, v0.y);
            a[mt][ks][2] = packh2(v0.z, v0.w);
            a[mt][ks][1] = packh2(v1.x, v1.y);
            a[mt][ks][3] = packh2(v1.z, v1.w);
        }
    }
    for (int i = tid; i < NQ; i += 128) sm.cc[i] = g_cc[quarter * NQ + i];

    float rmin[2][2] = {{__int_as_float(0x7f800000), __int_as_float(0x7f800000)},
                        {__int_as_float(0x7f800000), __int_as_float(0x7f800000)}};

    for (int t = 0; t < NTILES; t++) {
        if (t + 1 < NTILES) {
            load_B(sm, quarter * NTILES + t + 1, (t + 1) & 1, tid);
            cpwait<1>();
        } else {
            cpwait<0>();
        }
        __syncthreads();

        const uint4* Bb = sm.B[t & 1];

        #pragma unroll
        for (int grp = 0; grp < 2; grp++) {
            float c[2][4][4];
            #pragma unroll
            for (int mt = 0; mt < 2; mt++)
                #pragma unroll
                for (int u = 0; u < 4; u++)
                    c[mt][u][0] = c[mt][u][1] = c[mt][u][2] = c[mt][u][3] = 0.f;

            #pragma unroll
            for (int ksp = 0; ksp < 8; ksp++) {
                uint4 bw[4];
                #pragma unroll
                for (int u = 0; u < 4; u++)
                    bw[u] = Bb[((grp * 8 + ksp) * 4 + u) * 32 + lane];  // LDS.128

                #pragma unroll
                for (int u = 0; u < 4; u++) {
                    mma_f16f32(c[0][u], a[0][2 * ksp],     bw[u].x, bw[u].y);
                    mma_f16f32(c[1][u], a[1][2 * ksp],     bw[u].x, bw[u].y);
                    mma_f16f32(c[0][u], a[0][2 * ksp + 1], bw[u].z, bw[u].w);
                    mma_f16f32(c[1][u], a[1][2 * ksp + 1], bw[u].z, bw[u].w);
                }
            }

            // decode epilogue: each acc column carries 2 refs (comb = d0+1024*d1)
            #pragma unroll
            for (int u = 0; u < 4; u++) {
                int n0 = t * 64 + (grp * 4 + u) * 8 + q * 2;   // local packed col
                float2 ccv = *reinterpret_cast<const float2*>(&sm.cc[n0]);
                #pragma unroll
                for (int mt = 0; mt < 2; mt++) {
                    decode_min(c[mt][u][0], ccv.x, rmin[mt][0]);
                    decode_min(c[mt][u][1], ccv.y, rmin[mt][0]);
                    decode_min(c[mt][u][2], ccv.x, rmin[mt][1]);
                    decode_min(c[mt][u][3], ccv.y, rmin[mt][1]);
                }
            }
        }
        __syncthreads();
    }

    // combine quads; quarters via int atomicMin on float bits (all >= 0)
    #pragma unroll
    for (int mt = 0; mt < 2; mt++) {
        #pragma unroll
        for (int h = 0; h < 2; h++) {
            float v = rmin[mt][h];
            v = fminf(v, __shfl_xor_sync(0xffffffffu, v, 1));
            v = fminf(v, __shfl_xor_sync(0xffffffffu, v, 2));
            if (q == 0)
                atomicMin(&outi[mtile * MT + wid * 32 + mt * 16 + h * 8 + g],
                          __float_as_int(v));
        }
    }
}

// ---------------------------------------------------------------------------
extern "C" void kernel_launch(void* const* d_in, const int* in_sizes, int n_in,
                              void* d_out, int out_size) {
    const float* states = (const float*)d_in[0];
    const float* R      = (const float*)d_in[1];
    int* outi           = (int*)d_out;

    prep_kernel<<<256, 256>>>(R, outi);          // 65536 threads

    cudaFuncSetAttribute(hamming_fr, cudaFuncAttributeMaxDynamicSharedMemorySize, SMEM_SZ);
    hamming_fr<<<GRID, 128, SMEM_SZ>>>(states, outi);
}

// round 16
// speedup vs baseline: 1.7851x; 1.0107x over previous
#include <cuda_runtime.h>
#include <cuda_fp16.h>
#include <cstdint>

#define BATCH 8192
#define NREF  2048
#define KDIM  256
#define MT    128             // M rows per mtile (4 warps x 32 rows)
#define NM    64              // mtiles
#define NPACK 1024            // packed columns total (2 refs each)
#define NT    32              // packed cols per work item
#define NCH   32              // chunks (NPACK / NT)
#define NITEMS (NM * NCH)     // 2048 items, mtile-major
#define GRID  296             // 2 CTAs x 148 SMs, single balanced wave
#define TILE_B 16384          // bytes per B tile (32 cols x 512 B)

// g_B: fragment-order layout. Per chunk C (0..31):
//   [ksp(8)][u(4)][lane(32)] -> uint4 {b0,b1 @ks=2ksp, b0,b1 @ks=2ksp+1}
__device__ uint4 g_B[NPACK * KDIM / 8];    // 1 MB
__device__ float g_cc[NPACK];              // cntR[2n] + 1024*cntR[2n+1]

struct Smem {
    uint4 B[2][TILE_B / 16];  // 2 x 16384 B
    float cc[NPACK];          // all 1024 cc values (4096 B)
};
#define SMEM_SZ (int)sizeof(Smem)

// ---------------------------------------------------------------------------
__device__ __forceinline__ uint32_t s2u(const void* p) {
    uint32_t a;
    asm("{ .reg .u64 t; cvta.to.shared.u64 t, %1; cvt.u32.u64 %0, t; }" : "=r"(a) : "l"(p));
    return a;
}
__device__ __forceinline__ void cpa16(uint32_t dst, const void* src) {
    asm volatile("cp.async.cg.shared.global [%0], [%1], 16;" :: "r"(dst), "l"(src));
}
template <int N>
__device__ __forceinline__ void cpwait() {
    asm volatile("cp.async.wait_group %0;" :: "n"(N) : "memory");
}
__device__ __forceinline__ void mma_f16f32(float* c, const uint32_t* a,
                                           uint32_t b0, uint32_t b1) {
    asm volatile(
        "mma.sync.aligned.m16n8k16.row.col.f32.f16.f16.f32 "
        "{%0,%1,%2,%3},{%4,%5,%6,%7},{%8,%9},{%0,%1,%2,%3};"
        : "+f"(c[0]), "+f"(c[1]), "+f"(c[2]), "+f"(c[3])
        : "r"(a[0]), "r"(a[1]), "r"(a[2]), "r"(a[3]), "r"(b0), "r"(b1));
}
__device__ __forceinline__ uint32_t packh2(float x, float y) {
    __half2 h = __floats2half2_rn(x, y);
    return *reinterpret_cast<uint32_t*>(&h);
}
// decode packed distance: comb = d0 + 1024*d1, d0,d1 in [0,256] (exact)
__device__ __forceinline__ void decode_min(float acc, float ccv, float& rmin) {
    float comb = acc + ccv;
    float d1 = rintf(comb * (1.0f / 1024.0f));     // d0/1024 <= 0.25 -> no ties
    float d0 = fmaf(d1, -1024.0f, comb);           // exact
    rmin = fminf(rmin, fminf(d0, d1));
}

// ---------------------------------------------------------------------------
// Kernel 1 (prep): out init; fragment-order radix-1024 B pack; cc.
//   val(n,k) = 1025 - 2*R[2n][k] - 2048*R[2n+1][k]  in {+-1023,+-1025} (exact)
// ---------------------------------------------------------------------------
__global__ void prep_kernel(const float* __restrict__ R, int* __restrict__ outi) {
    int i = blockIdx.x * 256 + threadIdx.x;      // 65536 threads

    if (i < BATCH) outi[i] = 0x7f800000;         // +inf bits

    if (i < 32768) {
        // one uint4 of fragment-order B per thread
        int C    = i >> 10;                      // chunk 0..31
        int r    = i & 1023;
        int ksp  = r >> 7;
        int u    = (r >> 5) & 3;
        int lane = r & 31;
        int g    = lane >> 2, q = lane & 3;
        int n    = C * NT + u * 8 + g;           // packed col
        int kk0  = ksp * 32 + q * 4;

        const float* r0 = R + (size_t)(2 * n) * KDIM;
        const float* r1 = r0 + KDIM;
        float4 a0 = *reinterpret_cast<const float4*>(r0 + kk0);
        float4 a1 = *reinterpret_cast<const float4*>(r0 + kk0 + 16);
        float4 b0 = *reinterpret_cast<const float4*>(r1 + kk0);
        float4 b1 = *reinterpret_cast<const float4*>(r1 + kk0 + 16);

        uint4 o;
        o.x = packh2(1025.f - 2.f * a0.x - 2048.f * b0.x,
                     1025.f - 2.f * a0.y - 2048.f * b0.y);
        o.y = packh2(1025.f - 2.f * a0.z - 2048.f * b0.z,
                     1025.f - 2.f * a0.w - 2048.f * b0.w);
        o.z = packh2(1025.f - 2.f * a1.x - 2048.f * b1.x,
                     1025.f - 2.f * a1.y - 2048.f * b1.y);
        o.w = packh2(1025.f - 2.f * a1.z - 2048.f * b1.z,
                     1025.f - 2.f * a1.w - 2048.f * b1.w);
        g_B[i] = o;
    } else {
        // cc: one warp per packed col (1024 warps)
        int t = i - 32768;
        int n = t >> 5, lane = t & 31;
        const float* r0 = R + (size_t)(2 * n) * KDIM;
        float s0 = 0.f, s1 = 0.f;
        #pragma unroll
        for (int k = lane; k < KDIM; k += 32) {
            s0 += r0[k];
            s1 += r0[KDIM + k];
        }
        float s = s0 + 1024.f * s1;
        #pragma unroll
        for (int o = 16; o; o >>= 1) s += __shfl_xor_sync(0xffffffffu, s, o);
        if (lane == 0) g_cc[n] = s;
    }
}

// ---------------------------------------------------------------------------
// Kernel 2 (main): balanced static partition of 2048 (mtile, chunk) items
// over 296 CTAs; fragment-order B (LDS.128); 2-buffer cp.async; decode min.
// ---------------------------------------------------------------------------
__device__ __forceinline__ void load_B(Smem& sm, int item, int buf, int tid) {
    int chunk = item & (NCH - 1);
    const char* src = (const char*)g_B + (size_t)chunk * TILE_B;
    uint32_t dst = s2u(&sm.B[buf][0]);
    #pragma unroll
    for (int j = 0; j < 8; j++) {                // 1024 x 16B / 128 threads
        int i = tid + j * 128;
        cpa16(dst + i * 16, src + (size_t)i * 16);
    }
    asm volatile("cp.async.commit_group;" ::: "memory");
}

__global__ void __launch_bounds__(128, 2) hamming_bal(const float* __restrict__ S,
                                                      int* __restrict__ outi) {
    extern __shared__ __align__(16) char smraw[];
    Smem& sm = *reinterpret_cast<Smem*>(smraw);

    const int tid  = threadIdx.x;
    const int wid  = tid >> 5;
    const int lane = tid & 31;
    const int g    = lane >> 2;
    const int q    = lane & 3;

    // static contiguous item range (2048/296 = 256/37)
    const int start = (blockIdx.x * 256) / 37;
    const int end   = ((blockIdx.x + 1) * 256) / 37;
    int cur_m = start >> 5;

    load_B(sm, start, 0, tid);                   // first tile in flight

    // all 1024 cc values into smem
    for (int i = tid; i < NPACK / 4; i += 128)
        *reinterpret_cast<float4*>(&sm.cc[i * 4]) =
            *reinterpret_cast<const float4*>(&g_cc[i * 4]);

    // A fragments: 2 m16-tiles x 16 ks x 4 regs, contiguous float4 loads
    uint32_t a[2][16][4];
    auto loadA = [&](int m) {
        #pragma unroll
        for (int mt = 0; mt < 2; mt++) {
            const float* rowLo = S + ((size_t)(m * MT + wid * 32 + mt * 16 + g)) * KDIM;
            const float* rowHi = rowLo + 8 * KDIM;
            #pragma unroll
            for (int ks = 0; ks < 16; ks++) {
                float4 v0 = *reinterpret_cast<const float4*>(rowLo + ks * 16 + q * 4);
                float4 v1 = *reinterpret_cast<const float4*>(rowHi + ks * 16 + q * 4);
                a[mt][ks][0] = packh2(v0.x, v0.y);
                a[mt][ks][2] = packh2(v0.z, v0.w);
                a[mt][ks][1] = packh2(v1.x, v1.y);
                a[mt][ks][3] = packh2(v1.z, v1.w);
            }
        }
    };
    loadA(cur_m);

    float rmin[2][2] = {{__int_as_float(0x7f800000), __int_as_float(0x7f800000)},
                        {__int_as_float(0x7f800000), __int_as_float(0x7f800000)}};

    auto flush = [&](int m) {
        #pragma unroll
        for (int mt = 0; mt < 2; mt++)
            #pragma unroll
            for (int h = 0; h < 2; h++) {
                float v = rmin[mt][h];
                v = fminf(v, __shfl_xor_sync(0xffffffffu, v, 1));
                v = fminf(v, __shfl_xor_sync(0xffffffffu, v, 2));
                if (q == 0)
                    atomicMin(&outi[m * MT + wid * 32 + mt * 16 + h * 8 + g],
                              __float_as_int(v));
                rmin[mt][h] = __int_as_float(0x7f800000);
            }
    };

    int buf = 0;
    for (int it = start; it < end; it++) {
        if (it + 1 < end) {
            load_B(sm, it + 1, buf ^ 1, tid);
            cpwait<1>();
        } else {
            cpwait<0>();
        }
        __syncthreads();

        const uint4* Bb = sm.B[buf];
        float c[2][4][4];
        #pragma unroll
        for (int mt = 0; mt < 2; mt++)
            #pragma unroll
            for (int u = 0; u < 4; u++)
                c[mt][u][0] = c[mt][u][1] = c[mt][u][2] = c[mt][u][3] = 0.f;

        #pragma unroll
        for (int ksp = 0; ksp < 8; ksp++) {
            uint4 bw[4];
            #pragma unroll
            for (int u = 0; u < 4; u++)
                bw[u] = Bb[(ksp * 4 + u) * 32 + lane];        // LDS.128

            #pragma unroll
            for (int u = 0; u < 4; u++) {
                mma_f16f32(c[0][u], a[0][2 * ksp],     bw[u].x, bw[u].y);
                mma_f16f32(c[1][u], a[1][2 * ksp],     bw[u].x, bw[u].y);
                mma_f16f32(c[0][u], a[0][2 * ksp + 1], bw[u].z, bw[u].w);
                mma_f16f32(c[1][u], a[1][2 * ksp + 1], bw[u].z, bw[u].w);
            }
        }

        // decode epilogue (acc column = 2 refs; comb = d0 + 1024*d1)
        {
            int cc0 = (it & (NCH - 1)) * NT;
            #pragma unroll
            for (int u = 0; u < 4; u++) {
                float2 ccv = *reinterpret_cast<const float2*>(&sm.cc[cc0 + u * 8 + q * 2]);
                #pragma unroll
                for (int mt = 0; mt < 2; mt++) {
                    decode_min(c[mt][u][0], ccv.x, rmin[mt][0]);
                    decode_min(c[mt][u][1], ccv.y, rmin[mt][0]);
                    decode_min(c[mt][u][2], ccv.x, rmin[mt][1]);
                    decode_min(c[mt][u][3], ccv.y, rmin[mt][1]);
                }
            }
        }
        __syncthreads();          // done with sm.B[buf]; safe to refill

        if (it + 1 < end) {
            int nm = (it + 1) >> 5;
            if (nm != cur_m) { flush(cur_m); loadA(nm); cur_m = nm; }
        }
        buf ^= 1;
    }
    flush(cur_m);
}

// ---------------------------------------------------------------------------
extern "C" void kernel_launch(void* const* d_in, const int* in_sizes, int n_in,
                              void* d_out, int out_size) {
    const float* states = (const float*)d_in[0];
    const float* R      = (const float*)d_in[1];
    int* outi           = (int*)d_out;

    prep_kernel<<<256, 256>>>(R, outi);          // 65536 threads

    cudaFuncSetAttribute(hamming_bal, cudaFuncAttributeMaxDynamicSharedMemorySize, SMEM_SZ);
    hamming_bal<<<GRID, 128, SMEM_SZ>>>(states, outi);
}